// round 5
// baseline (speedup 1.0000x reference)
#include <cuda_runtime.h>
#include <float.h>

// Problem constants (fixed by the dataset)
#define N_  2
#define C_  256
#define H_  56
#define W_  56
#define R_  512
#define P_  7
#define SCALE_ 0.0625f
#define CHALF_ 128
#define PLANE_ (H_ * W_)

// Window-union extent <= roi_dim + 1 <= 23 (fp rounding can push hend(6)
// one past roi bottom). Tile 24 rows, stride 25 (odd -> bank spread).
#define TROWS   24
#define TSTRIDE 25
#define WPB     8             // warps per block

__global__ __launch_bounds__(256) void roipool_kernel(
    const float* __restrict__ features,
    const float* __restrict__ rois,
    float* __restrict__ out)
{
    __shared__ float tiles[WPB][2][TROWS * TSTRIDE];   // 38400 B

    const int lane = threadIdx.x & 31;
    const int warp = threadIdx.x >> 5;
    const int wid  = blockIdx.x * WPB + warp;   // one warp per (r, c<128)
    const int r = wid >> 7;                     // / CHALF_
    const int c = wid & (CHALF_ - 1);           // % CHALF_

    // ---- ROI math (warp-uniform; fp32 ops must MATCH the per-bin math) ----
    const float* roi = rois + r * 5;
    const int b  = (int)roi[0];                      // trunc == astype(int32)
    const int x1 = __float2int_rn(roi[1] * SCALE_);  // half-even == jnp.round
    const int y1 = __float2int_rn(roi[2] * SCALE_);
    const int x2 = __float2int_rn(roi[3] * SCALE_);
    const int y2 = __float2int_rn(roi[4] * SCALE_);

    const float bin_h = (float)max(y2 - y1 + 1, 1) * (1.0f / P_);
    const float bin_w = (float)max(x2 - x1 + 1, 1) * (1.0f / P_);

    // Region = [hstart(0), hend(6)) x [wstart(0), wend(6)) — exact union
    // bound of all bin windows, computed with IDENTICAL float expressions.
    const int y_lo = min(max((int)floorf(0.0f * bin_h) + y1, 0), H_);
    const int y_hi = min(max((int)ceilf ((float)P_ * bin_h) + y1, 0), H_);
    const int x_lo = min(max((int)floorf(0.0f * bin_w) + x1, 0), W_);
    const int x_hi = min(max((int)ceilf ((float)P_ * bin_w) + x1, 0), W_);

    const int nrows = min(max(y_hi - y_lo, 0), TROWS);   // clamp = smem safety
    const int ncols = min(max(x_hi - x_lo, 0), TROWS);
    const int total = nrows * ncols;

    const float* planeA = features + ((size_t)b * C_ + c) * PLANE_;
    const float* planeB = planeA + (size_t)CHALF_ * PLANE_;
    float* tA = tiles[warp][0];
    float* tB = tiles[warp][1];

    // ---- cooperative, coalesced region load into SMEM (both channels) ----
    for (int li = lane; li < total; li += 32) {
        int row = li / ncols;                 // ncols warp-uniform
        int col = li - row * ncols;
        int g   = (y_lo + row) * W_ + x_lo + col;
        tA[row * TSTRIDE + col] = __ldg(planeA + g);
        tB[row * TSTRIDE + col] = __ldg(planeB + g);
    }
    __syncwarp();

    const size_t obase = ((size_t)r * C_ + c) * (P_ * P_);

    // ---- 49 bins over 32 lanes (2 passes); reads from SMEM ----
    #pragma unroll
    for (int pass = 0; pass < 2; ++pass) {
        int bin = lane + pass * 32;
        if (bin < P_ * P_) {
            int ph = bin / P_;
            int pw = bin - ph * P_;

            int hs = min(max((int)floorf((float)ph       * bin_h) + y1, 0), H_);
            int he = min(max((int)ceilf ((float)(ph + 1) * bin_h) + y1, 0), H_);
            int ws = min(max((int)floorf((float)pw       * bin_w) + x1, 0), W_);
            int we = min(max((int)ceilf ((float)(pw + 1) * bin_w) + x1, 0), W_);

            int dh = he - hs, dw = we - ws;
            bool empty = (dh <= 0) || (dw <= 0);

            float mA = -FLT_MAX, mB = -FLT_MAX;
            int base = (hs - y_lo) * TSTRIDE + (ws - x_lo);
            for (int i = 0; i < dh; ++i) {
                int rowo = base + i * TSTRIDE;
                for (int j = 0; j < dw; ++j) {
                    mA = fmaxf(mA, tA[rowo + j]);
                    mB = fmaxf(mB, tB[rowo + j]);
                }
            }

            out[obase + bin]                            = empty ? 0.0f : mA;
            out[obase + (size_t)CHALF_ * P_ * P_ + bin] = empty ? 0.0f : mB;
        }
    }
}

extern "C" void kernel_launch(void* const* d_in, const int* in_sizes, int n_in,
                              void* d_out, int out_size)
{
    const float* features = (const float*)d_in[0];
    const float* rois     = (const float*)d_in[1];
    float* out            = (float*)d_out;

    int grid = (R_ * CHALF_) / WPB;   // 8192 blocks, 1 warp per (r, c-pair)
    roipool_kernel<<<grid, WPB * 32>>>(features, rois, out);
}